// round 6
// baseline (speedup 1.0000x reference)
#include <cuda_runtime.h>

#define N_NODES 320000
#define F_IN    128
#define L       10
#define CAP     80
#define N_EDGES 10240000
#define FULL    0xffffffffu

static __device__ int    g_cnt[N_NODES];
static __device__ float  g_dis[N_NODES];
static __device__ float4 g_hwA[(size_t)N_NODES * 4];   // 16-float padded rows (64B)
static __device__ float4 g_hwB[(size_t)N_NODES * 4];
static __device__ int    g_csr[(size_t)N_NODES * CAP];

// ---------------------------------------------------------------------------
// 1) Bucket scatter, 4 independent edges per thread (ILP over ATOMG latency)
// ---------------------------------------------------------------------------
#define EQ (N_EDGES / 4)
__global__ void k_scatter(const int* __restrict__ ei) {
    int e = blockIdx.x * blockDim.x + threadIdx.x;
    if (e >= EQ) return;
    const int* rp = ei;
    const int* cp = ei + N_EDGES;
    int r0 = __ldg(&rp[e]);
    int r1 = __ldg(&rp[e + EQ]);
    int r2 = __ldg(&rp[e + 2 * EQ]);
    int r3 = __ldg(&rp[e + 3 * EQ]);
    int c0 = __ldg(&cp[e]);
    int c1 = __ldg(&cp[e + EQ]);
    int c2 = __ldg(&cp[e + 2 * EQ]);
    int c3 = __ldg(&cp[e + 3 * EQ]);
    int p0 = atomicAdd(&g_cnt[c0], 1);
    int p1 = atomicAdd(&g_cnt[c1], 1);
    int p2 = atomicAdd(&g_cnt[c2], 1);
    int p3 = atomicAdd(&g_cnt[c3], 1);
    if (p0 < CAP) g_csr[(size_t)c0 * CAP + p0] = r0;
    if (p1 < CAP) g_csr[(size_t)c1 * CAP + p1] = r1;
    if (p2 < CAP) g_csr[(size_t)c2 * CAP + p2] = r2;
    if (p3 < CAP) g_csr[(size_t)c3 * CAP + p3] = r3;
}

// ---------------------------------------------------------------------------
// 2) Input, smem-staged x: dis = rsqrt(deg+2); hwA = dis*(relu(x@Win+bin)@W1)
//    128 thr/block, 128 nodes/block. x tile staged coalesced into smem with
//    stride-129 padding -> conflict-free scalar LDS on compute.
// ---------------------------------------------------------------------------
#define XSTR 129
__global__ void k_input(const float* __restrict__ x, const float* __restrict__ Win,
                        const float* __restrict__ bin, const float* __restrict__ W1) {
    extern __shared__ float sm[];
    float* sX  = sm;                         // 128 * 129
    float* sW  = sX + 128 * XSTR;            // 128 * 10
    float* sB  = sW + F_IN * L;              // 16
    float* sW1 = sB + 16;                    // 10 * 10

    int tid = threadIdx.x;
    for (int i = tid; i < F_IN * L; i += 128) sW[i] = Win[i];
    for (int i = tid; i < L * L;   i += 128) sW1[i] = W1[i];
    if (tid < L) sB[tid] = bin[tid];

    int nb = blockIdx.x * 128;
    // stage 128 rows x 128 floats, coalesced float4 loads
    const float4* xb = (const float4*)(x + (size_t)nb * F_IN);
    #pragma unroll
    for (int it = 0; it < 32; it++) {
        int f   = tid + it * 128;            // float4 index within tile
        int row = f >> 5;
        int q   = f & 31;
        float4 v = __ldg(&xb[row * 32 + q]);
        float* d = &sX[row * XSTR + q * 4];
        d[0] = v.x; d[1] = v.y; d[2] = v.z; d[3] = v.w;
    }
    __syncthreads();

    int n = nb + tid;
    const float* xr = &sX[tid * XSTR];

    float acc[L];
    #pragma unroll
    for (int j = 0; j < L; j++) acc[j] = 0.f;

    #pragma unroll 4
    for (int k = 0; k < F_IN; k += 4) {
        float v0 = xr[k], v1 = xr[k+1], v2 = xr[k+2], v3 = xr[k+3];
        #pragma unroll
        for (int j = 0; j < L; j++) {
            acc[j] = fmaf(v0, sW[(k  ) * L + j], acc[j]);
            acc[j] = fmaf(v1, sW[(k+1) * L + j], acc[j]);
            acc[j] = fmaf(v2, sW[(k+2) * L + j], acc[j]);
            acc[j] = fmaf(v3, sW[(k+3) * L + j], acc[j]);
        }
    }

    float h[L];
    #pragma unroll
    for (int j = 0; j < L; j++) h[j] = fmaxf(acc[j] + sB[j], 0.f);

    float t[L];
    #pragma unroll
    for (int j = 0; j < L; j++) t[j] = 0.f;
    #pragma unroll
    for (int l = 0; l < L; l++) {
        #pragma unroll
        for (int j = 0; j < L; j++)
            t[j] = fmaf(h[l], sW1[l * L + j], t[j]);
    }

    float d = rsqrtf((float)g_cnt[n] + 2.0f);
    g_dis[n] = d;
    float4* o = &g_hwA[(size_t)n * 4];
    o[0] = make_float4(d*t[0], d*t[1], d*t[2], d*t[3]);
    o[1] = make_float4(d*t[4], d*t[5], d*t[6], d*t[7]);
    o[2] = make_float4(d*t[8], d*t[9], 0.f, 0.f);
    o[3] = make_float4(0.f, 0.f, 0.f, 0.f);
}

// ---------------------------------------------------------------------------
// 3) Layer-1 gather, warp/node, 4 lanes/edge:
//    h = relu(dis*(Σ hwA[r] + 2*hwA[n]) + b1);  hwB[n] = dis * (h @ W2)
// ---------------------------------------------------------------------------
__global__ void k_gmid(const float* __restrict__ b1, const float* __restrict__ W2) {
    __shared__ float sW[L * 16];
    __shared__ float sB[16];
    for (int i = threadIdx.x; i < L * 16; i += blockDim.x) {
        int l = i >> 4, j = i & 15;
        sW[i] = (j < L) ? W2[l * L + j] : 0.f;
    }
    if (threadIdx.x < 16) sB[threadIdx.x] = (threadIdx.x < L) ? b1[threadIdx.x] : 0.f;
    __syncthreads();

    int n = (blockIdx.x * blockDim.x + threadIdx.x) >> 5;
    if (n >= N_NODES) return;
    int lane = threadIdx.x & 31;
    int sub  = lane >> 2;
    int c    = lane & 3;

    int cnt = g_cnt[n];
    if (cnt > CAP) cnt = CAP;
    const int* bucket = &g_csr[(size_t)n * CAP];

    float4 acc = make_float4(0.f, 0.f, 0.f, 0.f);
    int i = sub;
    for (; i + 8 < cnt; i += 16) {
        int r0 = __ldg(&bucket[i]);
        int r1 = __ldg(&bucket[i + 8]);
        float4 v0 = __ldg(&g_hwA[(size_t)r0 * 4 + c]);
        float4 v1 = __ldg(&g_hwA[(size_t)r1 * 4 + c]);
        acc.x += v0.x + v1.x; acc.y += v0.y + v1.y;
        acc.z += v0.z + v1.z; acc.w += v0.w + v1.w;
    }
    if (i < cnt) {
        int r = __ldg(&bucket[i]);
        float4 v = __ldg(&g_hwA[(size_t)r * 4 + c]);
        acc.x += v.x; acc.y += v.y; acc.z += v.z; acc.w += v.w;
    }
    #pragma unroll
    for (int s = 4; s < 32; s <<= 1) {
        acc.x += __shfl_xor_sync(FULL, acc.x, s);
        acc.y += __shfl_xor_sync(FULL, acc.y, s);
        acc.z += __shfl_xor_sync(FULL, acc.z, s);
        acc.w += __shfl_xor_sync(FULL, acc.w, s);
    }

    float dis = g_dis[n];
    float4 self = __ldg(&g_hwA[(size_t)n * 4 + c]);
    float4 hv;
    hv.x = fmaxf(dis * (acc.x + 2.f * self.x) + sB[c * 4 + 0], 0.f);
    hv.y = fmaxf(dis * (acc.y + 2.f * self.y) + sB[c * 4 + 1], 0.f);
    hv.z = fmaxf(dis * (acc.z + 2.f * self.z) + sB[c * 4 + 2], 0.f);
    hv.w = fmaxf(dis * (acc.w + 2.f * self.w) + sB[c * 4 + 3], 0.f);

    float h[L];
    h[0] = __shfl_sync(FULL, hv.x, 0); h[1] = __shfl_sync(FULL, hv.y, 0);
    h[2] = __shfl_sync(FULL, hv.z, 0); h[3] = __shfl_sync(FULL, hv.w, 0);
    h[4] = __shfl_sync(FULL, hv.x, 1); h[5] = __shfl_sync(FULL, hv.y, 1);
    h[6] = __shfl_sync(FULL, hv.z, 1); h[7] = __shfl_sync(FULL, hv.w, 1);
    h[8] = __shfl_sync(FULL, hv.x, 2); h[9] = __shfl_sync(FULL, hv.y, 2);

    if (sub != 0) return;
    float4 t = make_float4(0.f, 0.f, 0.f, 0.f);
    #pragma unroll
    for (int l = 0; l < L; l++) {
        float4 w = *(const float4*)&sW[l * 16 + c * 4];
        t.x = fmaf(h[l], w.x, t.x);
        t.y = fmaf(h[l], w.y, t.y);
        t.z = fmaf(h[l], w.z, t.z);
        t.w = fmaf(h[l], w.w, t.w);
    }
    t.x *= dis; t.y *= dis; t.z *= dis; t.w *= dis;
    g_hwB[(size_t)n * 4 + c] = t;
}

// ---------------------------------------------------------------------------
// 4) Layer-2 gather + output
// ---------------------------------------------------------------------------
__global__ void k_gout(const float* __restrict__ b2, const float* __restrict__ Wout,
                       const float* __restrict__ bout, float* __restrict__ out) {
    __shared__ float sWo[16];
    __shared__ float sB[16];
    __shared__ float sb0;
    if (threadIdx.x < 16) {
        sWo[threadIdx.x] = (threadIdx.x < L) ? Wout[threadIdx.x] : 0.f;
        sB [threadIdx.x] = (threadIdx.x < L) ? b2[threadIdx.x]  : 0.f;
    }
    if (threadIdx.x == 0) sb0 = bout[0];
    __syncthreads();

    int n = (blockIdx.x * blockDim.x + threadIdx.x) >> 5;
    if (n >= N_NODES) return;
    int lane = threadIdx.x & 31;
    int sub  = lane >> 2;
    int c    = lane & 3;

    int cnt = g_cnt[n];
    if (cnt > CAP) cnt = CAP;
    const int* bucket = &g_csr[(size_t)n * CAP];

    float4 acc = make_float4(0.f, 0.f, 0.f, 0.f);
    int i = sub;
    for (; i + 8 < cnt; i += 16) {
        int r0 = __ldg(&bucket[i]);
        int r1 = __ldg(&bucket[i + 8]);
        float4 v0 = __ldg(&g_hwB[(size_t)r0 * 4 + c]);
        float4 v1 = __ldg(&g_hwB[(size_t)r1 * 4 + c]);
        acc.x += v0.x + v1.x; acc.y += v0.y + v1.y;
        acc.z += v0.z + v1.z; acc.w += v0.w + v1.w;
    }
    if (i < cnt) {
        int r = __ldg(&bucket[i]);
        float4 v = __ldg(&g_hwB[(size_t)r * 4 + c]);
        acc.x += v.x; acc.y += v.y; acc.z += v.z; acc.w += v.w;
    }
    #pragma unroll
    for (int s = 4; s < 32; s <<= 1) {
        acc.x += __shfl_xor_sync(FULL, acc.x, s);
        acc.y += __shfl_xor_sync(FULL, acc.y, s);
        acc.z += __shfl_xor_sync(FULL, acc.z, s);
        acc.w += __shfl_xor_sync(FULL, acc.w, s);
    }

    float dis = g_dis[n];
    float4 self = __ldg(&g_hwB[(size_t)n * 4 + c]);
    float4 hv;
    hv.x = fmaxf(dis * (acc.x + 2.f * self.x) + sB[c * 4 + 0], 0.f);
    hv.y = fmaxf(dis * (acc.y + 2.f * self.y) + sB[c * 4 + 1], 0.f);
    hv.z = fmaxf(dis * (acc.z + 2.f * self.z) + sB[c * 4 + 2], 0.f);
    hv.w = fmaxf(dis * (acc.w + 2.f * self.w) + sB[c * 4 + 3], 0.f);

    float part = hv.x * sWo[c*4+0] + hv.y * sWo[c*4+1]
               + hv.z * sWo[c*4+2] + hv.w * sWo[c*4+3];
    part += __shfl_xor_sync(FULL, part, 1);
    part += __shfl_xor_sync(FULL, part, 2);
    if (lane == 0) out[n] = part + sb0;
}

extern "C" void kernel_launch(void* const* d_in, const int* in_sizes, int n_in,
                              void* d_out, int out_size) {
    const float* x    = (const float*)d_in[0];
    const int*   ei   = (const int*)  d_in[1];
    const float* Win  = (const float*)d_in[2];
    const float* bin  = (const float*)d_in[3];
    const float* W1   = (const float*)d_in[4];
    const float* b1   = (const float*)d_in[5];
    const float* W2   = (const float*)d_in[6];
    const float* b2   = (const float*)d_in[7];
    const float* Wout = (const float*)d_in[8];
    const float* bout = (const float*)d_in[9];
    float* out = (float*)d_out;

    void* cnt_p = nullptr;
    cudaGetSymbolAddress(&cnt_p, g_cnt);

    const int TB = 256;
    int sb = (EQ + TB - 1) / TB;
    int gb = N_NODES / 8;

    // k_input dynamic smem: x tile (128*129) + Win (1280) + bias (16) + W1 (100)
    size_t smem_in = (size_t)(128 * XSTR + F_IN * L + 16 + L * L + 12) * sizeof(float);
    static int attr_done = 0;
    if (!attr_done) {
        cudaFuncSetAttribute(k_input, cudaFuncAttributeMaxDynamicSharedMemorySize,
                             (int)smem_in);
        attr_done = 1;
    }

    cudaMemsetAsync(cnt_p, 0, (size_t)N_NODES * sizeof(int));
    k_scatter<<<sb, TB>>>(ei);
    k_input  <<<N_NODES / 128, 128, smem_in>>>(x, Win, bin, W1);
    k_gmid   <<<gb, TB>>>(b1, W2);
    k_gout   <<<gb, TB>>>(b2, Wout, bout, out);
}

// round 7
// speedup vs baseline: 1.0653x; 1.0653x over previous
#include <cuda_runtime.h>

#define N_NODES 320000
#define F_IN    128
#define L       10
#define CAP     80
#define N_EDGES 10240000
#define FULL    0xffffffffu

static __device__ int    g_cnt[N_NODES];
static __device__ float  g_dis[N_NODES];
static __device__ float4 g_hwA[(size_t)N_NODES * 4];   // 16-float padded rows (64B)
static __device__ float4 g_hwB[(size_t)N_NODES * 4];
static __device__ int    g_csr[(size_t)N_NODES * CAP];

// ---------------------------------------------------------------------------
// 1) Bucket scatter (simple 1 edge/thread): cnt becomes degree
// ---------------------------------------------------------------------------
__global__ void k_scatter(const int* __restrict__ ei) {
    int e = blockIdx.x * blockDim.x + threadIdx.x;
    if (e >= N_EDGES) return;
    int r = ei[e];
    int c = ei[N_EDGES + e];
    int pos = atomicAdd(&g_cnt[c], 1);
    if (pos < CAP) g_csr[(size_t)c * CAP + pos] = r;
}

// ---------------------------------------------------------------------------
// 2) Input (graph-independent): hwA[n] = relu(x@Win + bin) @ W1   (UNSCALED)
//    Runs concurrently with k_scatter on a side stream.
// ---------------------------------------------------------------------------
__global__ void k_input(const float* __restrict__ x, const float* __restrict__ Win,
                        const float* __restrict__ bin, const float* __restrict__ W1) {
    __shared__ float sW[F_IN * L];
    __shared__ float sB[L];
    __shared__ float sW1[L * L];
    for (int i = threadIdx.x; i < F_IN * L; i += blockDim.x) sW[i] = Win[i];
    for (int i = threadIdx.x; i < L * L;   i += blockDim.x) sW1[i] = W1[i];
    if (threadIdx.x < L) sB[threadIdx.x] = bin[threadIdx.x];
    __syncthreads();

    int t  = blockIdx.x * blockDim.x + threadIdx.x;
    int n0 = 2 * t;
    if (n0 >= N_NODES) return;
    int n1 = n0 + 1;

    float acc0[L], acc1[L];
    #pragma unroll
    for (int j = 0; j < L; j++) { acc0[j] = 0.f; acc1[j] = 0.f; }

    const float4* x0 = (const float4*)(x + (size_t)n0 * F_IN);
    const float4* x1 = (const float4*)(x + (size_t)n1 * F_IN);

    #pragma unroll 4
    for (int kq = 0; kq < F_IN / 4; kq++) {
        float4 a = x0[kq];
        float4 b = x1[kq];
        float va[4] = {a.x, a.y, a.z, a.w};
        float vb[4] = {b.x, b.y, b.z, b.w};
        #pragma unroll
        for (int u = 0; u < 4; u++) {
            int k = kq * 4 + u;
            #pragma unroll
            for (int j = 0; j < L; j++) {
                float w = sW[k * L + j];
                acc0[j] = fmaf(va[u], w, acc0[j]);
                acc1[j] = fmaf(vb[u], w, acc1[j]);
            }
        }
    }

    float h0[L], h1[L];
    #pragma unroll
    for (int j = 0; j < L; j++) {
        h0[j] = fmaxf(acc0[j] + sB[j], 0.f);
        h1[j] = fmaxf(acc1[j] + sB[j], 0.f);
    }

    float t0[L], t1[L];
    #pragma unroll
    for (int j = 0; j < L; j++) { t0[j] = 0.f; t1[j] = 0.f; }
    #pragma unroll
    for (int l = 0; l < L; l++) {
        #pragma unroll
        for (int j = 0; j < L; j++) {
            float w = sW1[l * L + j];
            t0[j] = fmaf(h0[l], w, t0[j]);
            t1[j] = fmaf(h1[l], w, t1[j]);
        }
    }

    float4* o0 = &g_hwA[(size_t)n0 * 4];
    float4* o1 = &g_hwA[(size_t)n1 * 4];
    o0[0] = make_float4(t0[0], t0[1], t0[2], t0[3]);
    o0[1] = make_float4(t0[4], t0[5], t0[6], t0[7]);
    o0[2] = make_float4(t0[8], t0[9], 0.f, 0.f);
    o0[3] = make_float4(0.f, 0.f, 0.f, 0.f);
    o1[0] = make_float4(t1[0], t1[1], t1[2], t1[3]);
    o1[1] = make_float4(t1[4], t1[5], t1[6], t1[7]);
    o1[2] = make_float4(t1[8], t1[9], 0.f, 0.f);
    o1[3] = make_float4(0.f, 0.f, 0.f, 0.f);
}

// ---------------------------------------------------------------------------
// 2b) Join kernel: dis = rsqrt(deg+2); hwA *= dis (quadrant-parallel, coalesced)
// ---------------------------------------------------------------------------
__global__ void k_scale() {
    int i = blockIdx.x * blockDim.x + threadIdx.x;      // float4 index
    if (i >= N_NODES * 4) return;
    int n = i >> 2;
    float dis = rsqrtf((float)g_cnt[n] + 2.0f);
    if ((i & 3) == 0) g_dis[n] = dis;
    float4 v = g_hwA[i];
    v.x *= dis; v.y *= dis; v.z *= dis; v.w *= dis;
    g_hwA[i] = v;
}

// ---------------------------------------------------------------------------
// 3) Layer-1 gather, warp/node, 4 lanes/edge:
//    h = relu(dis*(Σ hwA[r] + 2*hwA[n]) + b1);  hwB[n] = dis * (h @ W2)
// ---------------------------------------------------------------------------
__global__ void k_gmid(const float* __restrict__ b1, const float* __restrict__ W2) {
    __shared__ float sW[L * 16];
    __shared__ float sB[16];
    for (int i = threadIdx.x; i < L * 16; i += blockDim.x) {
        int l = i >> 4, j = i & 15;
        sW[i] = (j < L) ? W2[l * L + j] : 0.f;
    }
    if (threadIdx.x < 16) sB[threadIdx.x] = (threadIdx.x < L) ? b1[threadIdx.x] : 0.f;
    __syncthreads();

    int n = (blockIdx.x * blockDim.x + threadIdx.x) >> 5;
    if (n >= N_NODES) return;
    int lane = threadIdx.x & 31;
    int sub  = lane >> 2;
    int c    = lane & 3;

    int cnt = g_cnt[n];
    if (cnt > CAP) cnt = CAP;
    const int* bucket = &g_csr[(size_t)n * CAP];

    float4 acc = make_float4(0.f, 0.f, 0.f, 0.f);
    for (int i = sub; i < cnt; i += 8) {
        int r = __ldg(&bucket[i]);
        float4 v = __ldg(&g_hwA[(size_t)r * 4 + c]);
        acc.x += v.x; acc.y += v.y; acc.z += v.z; acc.w += v.w;
    }
    #pragma unroll
    for (int s = 4; s < 32; s <<= 1) {
        acc.x += __shfl_xor_sync(FULL, acc.x, s);
        acc.y += __shfl_xor_sync(FULL, acc.y, s);
        acc.z += __shfl_xor_sync(FULL, acc.z, s);
        acc.w += __shfl_xor_sync(FULL, acc.w, s);
    }

    float dis = g_dis[n];
    float4 self = __ldg(&g_hwA[(size_t)n * 4 + c]);
    float4 hv;
    hv.x = fmaxf(dis * (acc.x + 2.f * self.x) + sB[c * 4 + 0], 0.f);
    hv.y = fmaxf(dis * (acc.y + 2.f * self.y) + sB[c * 4 + 1], 0.f);
    hv.z = fmaxf(dis * (acc.z + 2.f * self.z) + sB[c * 4 + 2], 0.f);
    hv.w = fmaxf(dis * (acc.w + 2.f * self.w) + sB[c * 4 + 3], 0.f);

    float h[L];
    h[0] = __shfl_sync(FULL, hv.x, 0); h[1] = __shfl_sync(FULL, hv.y, 0);
    h[2] = __shfl_sync(FULL, hv.z, 0); h[3] = __shfl_sync(FULL, hv.w, 0);
    h[4] = __shfl_sync(FULL, hv.x, 1); h[5] = __shfl_sync(FULL, hv.y, 1);
    h[6] = __shfl_sync(FULL, hv.z, 1); h[7] = __shfl_sync(FULL, hv.w, 1);
    h[8] = __shfl_sync(FULL, hv.x, 2); h[9] = __shfl_sync(FULL, hv.y, 2);

    if (sub != 0) return;
    float4 t = make_float4(0.f, 0.f, 0.f, 0.f);
    #pragma unroll
    for (int l = 0; l < L; l++) {
        float4 w = *(const float4*)&sW[l * 16 + c * 4];
        t.x = fmaf(h[l], w.x, t.x);
        t.y = fmaf(h[l], w.y, t.y);
        t.z = fmaf(h[l], w.z, t.z);
        t.w = fmaf(h[l], w.w, t.w);
    }
    t.x *= dis; t.y *= dis; t.z *= dis; t.w *= dis;
    g_hwB[(size_t)n * 4 + c] = t;
}

// ---------------------------------------------------------------------------
// 4) Layer-2 gather + output
// ---------------------------------------------------------------------------
__global__ void k_gout(const float* __restrict__ b2, const float* __restrict__ Wout,
                       const float* __restrict__ bout, float* __restrict__ out) {
    __shared__ float sWo[16];
    __shared__ float sB[16];
    __shared__ float sb0;
    if (threadIdx.x < 16) {
        sWo[threadIdx.x] = (threadIdx.x < L) ? Wout[threadIdx.x] : 0.f;
        sB [threadIdx.x] = (threadIdx.x < L) ? b2[threadIdx.x]  : 0.f;
    }
    if (threadIdx.x == 0) sb0 = bout[0];
    __syncthreads();

    int n = (blockIdx.x * blockDim.x + threadIdx.x) >> 5;
    if (n >= N_NODES) return;
    int lane = threadIdx.x & 31;
    int sub  = lane >> 2;
    int c    = lane & 3;

    int cnt = g_cnt[n];
    if (cnt > CAP) cnt = CAP;
    const int* bucket = &g_csr[(size_t)n * CAP];

    float4 acc = make_float4(0.f, 0.f, 0.f, 0.f);
    for (int i = sub; i < cnt; i += 8) {
        int r = __ldg(&bucket[i]);
        float4 v = __ldg(&g_hwB[(size_t)r * 4 + c]);
        acc.x += v.x; acc.y += v.y; acc.z += v.z; acc.w += v.w;
    }
    #pragma unroll
    for (int s = 4; s < 32; s <<= 1) {
        acc.x += __shfl_xor_sync(FULL, acc.x, s);
        acc.y += __shfl_xor_sync(FULL, acc.y, s);
        acc.z += __shfl_xor_sync(FULL, acc.z, s);
        acc.w += __shfl_xor_sync(FULL, acc.w, s);
    }

    float dis = g_dis[n];
    float4 self = __ldg(&g_hwB[(size_t)n * 4 + c]);
    float4 hv;
    hv.x = fmaxf(dis * (acc.x + 2.f * self.x) + sB[c * 4 + 0], 0.f);
    hv.y = fmaxf(dis * (acc.y + 2.f * self.y) + sB[c * 4 + 1], 0.f);
    hv.z = fmaxf(dis * (acc.z + 2.f * self.z) + sB[c * 4 + 2], 0.f);
    hv.w = fmaxf(dis * (acc.w + 2.f * self.w) + sB[c * 4 + 3], 0.f);

    float part = hv.x * sWo[c*4+0] + hv.y * sWo[c*4+1]
               + hv.z * sWo[c*4+2] + hv.w * sWo[c*4+3];
    part += __shfl_xor_sync(FULL, part, 1);
    part += __shfl_xor_sync(FULL, part, 2);
    if (lane == 0) out[n] = part + sb0;
}

extern "C" void kernel_launch(void* const* d_in, const int* in_sizes, int n_in,
                              void* d_out, int out_size) {
    const float* x    = (const float*)d_in[0];
    const int*   ei   = (const int*)  d_in[1];
    const float* Win  = (const float*)d_in[2];
    const float* bin  = (const float*)d_in[3];
    const float* W1   = (const float*)d_in[4];
    const float* b1   = (const float*)d_in[5];
    const float* W2   = (const float*)d_in[6];
    const float* b2   = (const float*)d_in[7];
    const float* Wout = (const float*)d_in[8];
    const float* bout = (const float*)d_in[9];
    float* out = (float*)d_out;

    void* cnt_p = nullptr;
    cudaGetSymbolAddress(&cnt_p, g_cnt);

    // One-time host-side resources for the capture fork (no device memory).
    static cudaStream_t s1 = nullptr;
    static cudaEvent_t evFork = nullptr, evJoin = nullptr;
    if (s1 == nullptr) {
        cudaStreamCreateWithFlags(&s1, cudaStreamNonBlocking);
        cudaEventCreateWithFlags(&evFork, cudaEventDisableTiming);
        cudaEventCreateWithFlags(&evJoin, cudaEventDisableTiming);
    }

    const int TB = 256;
    int eb = (N_EDGES + TB - 1) / TB;
    int ib = (N_NODES / 2 + TB - 1) / TB;
    int sc = (N_NODES * 4 + TB - 1) / TB;
    int gb = N_NODES / 8;

    // Fork: side stream runs the graph-independent input GEMV chain
    cudaEventRecord(evFork, 0);
    cudaStreamWaitEvent(s1, evFork, 0);
    k_input<<<ib, TB, 0, s1>>>(x, Win, bin, W1);
    cudaEventRecord(evJoin, s1);

    // Main stream: build buckets (concurrent with k_input)
    cudaMemsetAsync(cnt_p, 0, (size_t)N_NODES * sizeof(int));
    k_scatter<<<eb, TB>>>(ei);

    // Join, then scale + gathers
    cudaStreamWaitEvent(0, evJoin, 0);
    k_scale<<<sc, TB>>>();
    k_gmid  <<<gb, TB>>>(b1, W2);
    k_gout  <<<gb, TB>>>(b2, Wout, bout, out);
}

// round 8
// speedup vs baseline: 1.1777x; 1.1055x over previous
#include <cuda_runtime.h>

#define N_NODES 320000
#define F_IN    128
#define L       10
#define CAP     80
#define N_EDGES 10240000
#define FULL    0xffffffffu

static __device__ int    g_cnt[N_NODES];
static __device__ float  g_dis[N_NODES];
static __device__ float4 g_hwA[(size_t)N_NODES * 4];   // 16-float padded rows (64B)
static __device__ float4 g_hwB[(size_t)N_NODES * 4];
static __device__ float4 g_agg[(size_t)N_NODES * 4];   // gather results
static __device__ int    g_csr[(size_t)N_NODES * CAP];

// ---------------------------------------------------------------------------
// 1) Bucket scatter (1 edge/thread): cnt becomes degree
// ---------------------------------------------------------------------------
__global__ void k_scatter(const int* __restrict__ ei) {
    int e = blockIdx.x * blockDim.x + threadIdx.x;
    if (e >= N_EDGES) return;
    int r = ei[e];
    int c = ei[N_EDGES + e];
    int pos = atomicAdd(&g_cnt[c], 1);
    if (pos < CAP) g_csr[(size_t)c * CAP + pos] = r;
}

// ---------------------------------------------------------------------------
// 2) Input (graph-independent, overlapped with scatter):
//    hwA[n] = relu(x@Win + bin) @ W1   (UNSCALED)
// ---------------------------------------------------------------------------
__global__ void k_input(const float* __restrict__ x, const float* __restrict__ Win,
                        const float* __restrict__ bin, const float* __restrict__ W1) {
    __shared__ float sW[F_IN * L];
    __shared__ float sB[L];
    __shared__ float sW1[L * L];
    for (int i = threadIdx.x; i < F_IN * L; i += blockDim.x) sW[i] = Win[i];
    for (int i = threadIdx.x; i < L * L;   i += blockDim.x) sW1[i] = W1[i];
    if (threadIdx.x < L) sB[threadIdx.x] = bin[threadIdx.x];
    __syncthreads();

    int t  = blockIdx.x * blockDim.x + threadIdx.x;
    int n0 = 2 * t;
    if (n0 >= N_NODES) return;
    int n1 = n0 + 1;

    float acc0[L], acc1[L];
    #pragma unroll
    for (int j = 0; j < L; j++) { acc0[j] = 0.f; acc1[j] = 0.f; }

    const float4* x0 = (const float4*)(x + (size_t)n0 * F_IN);
    const float4* x1 = (const float4*)(x + (size_t)n1 * F_IN);

    #pragma unroll 4
    for (int kq = 0; kq < F_IN / 4; kq++) {
        float4 a = x0[kq];
        float4 b = x1[kq];
        float va[4] = {a.x, a.y, a.z, a.w};
        float vb[4] = {b.x, b.y, b.z, b.w};
        #pragma unroll
        for (int u = 0; u < 4; u++) {
            int k = kq * 4 + u;
            #pragma unroll
            for (int j = 0; j < L; j++) {
                float w = sW[k * L + j];
                acc0[j] = fmaf(va[u], w, acc0[j]);
                acc1[j] = fmaf(vb[u], w, acc1[j]);
            }
        }
    }

    float h0[L], h1[L];
    #pragma unroll
    for (int j = 0; j < L; j++) {
        h0[j] = fmaxf(acc0[j] + sB[j], 0.f);
        h1[j] = fmaxf(acc1[j] + sB[j], 0.f);
    }

    float t0[L], t1[L];
    #pragma unroll
    for (int j = 0; j < L; j++) { t0[j] = 0.f; t1[j] = 0.f; }
    #pragma unroll
    for (int l = 0; l < L; l++) {
        #pragma unroll
        for (int j = 0; j < L; j++) {
            float w = sW1[l * L + j];
            t0[j] = fmaf(h0[l], w, t0[j]);
            t1[j] = fmaf(h1[l], w, t1[j]);
        }
    }

    float4* o0 = &g_hwA[(size_t)n0 * 4];
    float4* o1 = &g_hwA[(size_t)n1 * 4];
    o0[0] = make_float4(t0[0], t0[1], t0[2], t0[3]);
    o0[1] = make_float4(t0[4], t0[5], t0[6], t0[7]);
    o0[2] = make_float4(t0[8], t0[9], 0.f, 0.f);
    o0[3] = make_float4(0.f, 0.f, 0.f, 0.f);
    o1[0] = make_float4(t1[0], t1[1], t1[2], t1[3]);
    o1[1] = make_float4(t1[4], t1[5], t1[6], t1[7]);
    o1[2] = make_float4(t1[8], t1[9], 0.f, 0.f);
    o1[3] = make_float4(0.f, 0.f, 0.f, 0.f);
}

// ---------------------------------------------------------------------------
// 2b) Join: dis = rsqrt(deg+2); hwA *= dis
// ---------------------------------------------------------------------------
__global__ void k_scale() {
    int i = blockIdx.x * blockDim.x + threadIdx.x;      // float4 index
    if (i >= N_NODES * 4) return;
    int n = i >> 2;
    float dis = rsqrtf((float)g_cnt[n] + 2.0f);
    if ((i & 3) == 0) g_dis[n] = dis;
    float4 v = g_hwA[i];
    v.x *= dis; v.y *= dis; v.z *= dis; v.w *= dis;
    g_hwA[i] = v;
}

// ---------------------------------------------------------------------------
// 3) Pure gather: agg[n] = Σ_{r in bucket(n)} src[r]   (warp/node, 4 lanes/edge)
// ---------------------------------------------------------------------------
__global__ void k_gath(const float4* __restrict__ src) {
    int n = (blockIdx.x * blockDim.x + threadIdx.x) >> 5;
    if (n >= N_NODES) return;
    int lane = threadIdx.x & 31;
    int sub  = lane >> 2;
    int c    = lane & 3;

    int cnt = g_cnt[n];
    if (cnt > CAP) cnt = CAP;
    const int* bucket = &g_csr[(size_t)n * CAP];

    float4 acc = make_float4(0.f, 0.f, 0.f, 0.f);
    for (int i = sub; i < cnt; i += 8) {
        int r = __ldg(&bucket[i]);
        float4 v = __ldg(&src[(size_t)r * 4 + c]);
        acc.x += v.x; acc.y += v.y; acc.z += v.z; acc.w += v.w;
    }
    #pragma unroll
    for (int s = 4; s < 32; s <<= 1) {
        acc.x += __shfl_xor_sync(FULL, acc.x, s);
        acc.y += __shfl_xor_sync(FULL, acc.y, s);
        acc.z += __shfl_xor_sync(FULL, acc.z, s);
        acc.w += __shfl_xor_sync(FULL, acc.w, s);
    }
    if (lane < 4) g_agg[(size_t)n * 4 + c] = acc;       // 64B coalesced
}

// ---------------------------------------------------------------------------
// 4) Finalize layer 1 (thread/node, coalesced):
//    h = relu(dis*(agg + 2*hwA) + b1);  hwB = dis * (h @ W2)
// ---------------------------------------------------------------------------
__global__ void k_fin1(const float* __restrict__ b1, const float* __restrict__ W2) {
    __shared__ float sW[L * L];
    __shared__ float sB[L];
    for (int i = threadIdx.x; i < L * L; i += blockDim.x) sW[i] = W2[i];
    if (threadIdx.x < L) sB[threadIdx.x] = b1[threadIdx.x];
    __syncthreads();

    int n = blockIdx.x * blockDim.x + threadIdx.x;
    if (n >= N_NODES) return;

    float dis = g_dis[n];
    const float4* ag = &g_agg[(size_t)n * 4];
    const float4* hw = &g_hwA[(size_t)n * 4];
    float4 a0 = ag[0], a1 = ag[1], a2 = ag[2];
    float4 s0 = hw[0], s1 = hw[1], s2 = hw[2];

    float h[L];
    h[0] = fmaxf(dis * (a0.x + 2.f * s0.x) + sB[0], 0.f);
    h[1] = fmaxf(dis * (a0.y + 2.f * s0.y) + sB[1], 0.f);
    h[2] = fmaxf(dis * (a0.z + 2.f * s0.z) + sB[2], 0.f);
    h[3] = fmaxf(dis * (a0.w + 2.f * s0.w) + sB[3], 0.f);
    h[4] = fmaxf(dis * (a1.x + 2.f * s1.x) + sB[4], 0.f);
    h[5] = fmaxf(dis * (a1.y + 2.f * s1.y) + sB[5], 0.f);
    h[6] = fmaxf(dis * (a1.z + 2.f * s1.z) + sB[6], 0.f);
    h[7] = fmaxf(dis * (a1.w + 2.f * s1.w) + sB[7], 0.f);
    h[8] = fmaxf(dis * (a2.x + 2.f * s2.x) + sB[8], 0.f);
    h[9] = fmaxf(dis * (a2.y + 2.f * s2.y) + sB[9], 0.f);

    float t[L];
    #pragma unroll
    for (int j = 0; j < L; j++) t[j] = 0.f;
    #pragma unroll
    for (int l = 0; l < L; l++) {
        #pragma unroll
        for (int j = 0; j < L; j++)
            t[j] = fmaf(h[l], sW[l * L + j], t[j]);
    }

    float4* o = &g_hwB[(size_t)n * 4];
    o[0] = make_float4(dis*t[0], dis*t[1], dis*t[2], dis*t[3]);
    o[1] = make_float4(dis*t[4], dis*t[5], dis*t[6], dis*t[7]);
    o[2] = make_float4(dis*t[8], dis*t[9], 0.f, 0.f);
    o[3] = make_float4(0.f, 0.f, 0.f, 0.f);
}

// ---------------------------------------------------------------------------
// 5) Finalize layer 2 + output:
//    out = relu(dis*(agg + 2*hwB) + b2) @ Wout + bout
// ---------------------------------------------------------------------------
__global__ void k_fin2(const float* __restrict__ b2, const float* __restrict__ Wout,
                       const float* __restrict__ bout, float* __restrict__ out) {
    __shared__ float sWo[L];
    __shared__ float sB[L];
    __shared__ float sb0;
    if (threadIdx.x < L) { sWo[threadIdx.x] = Wout[threadIdx.x]; sB[threadIdx.x] = b2[threadIdx.x]; }
    if (threadIdx.x == 0) sb0 = bout[0];
    __syncthreads();

    int n = blockIdx.x * blockDim.x + threadIdx.x;
    if (n >= N_NODES) return;

    float dis = g_dis[n];
    const float4* ag = &g_agg[(size_t)n * 4];
    const float4* hw = &g_hwB[(size_t)n * 4];
    float4 a0 = ag[0], a1 = ag[1], a2 = ag[2];
    float4 s0 = hw[0], s1 = hw[1], s2 = hw[2];

    float acc = sb0;
    acc = fmaf(fmaxf(dis * (a0.x + 2.f * s0.x) + sB[0], 0.f), sWo[0], acc);
    acc = fmaf(fmaxf(dis * (a0.y + 2.f * s0.y) + sB[1], 0.f), sWo[1], acc);
    acc = fmaf(fmaxf(dis * (a0.z + 2.f * s0.z) + sB[2], 0.f), sWo[2], acc);
    acc = fmaf(fmaxf(dis * (a0.w + 2.f * s0.w) + sB[3], 0.f), sWo[3], acc);
    acc = fmaf(fmaxf(dis * (a1.x + 2.f * s1.x) + sB[4], 0.f), sWo[4], acc);
    acc = fmaf(fmaxf(dis * (a1.y + 2.f * s1.y) + sB[5], 0.f), sWo[5], acc);
    acc = fmaf(fmaxf(dis * (a1.z + 2.f * s1.z) + sB[6], 0.f), sWo[6], acc);
    acc = fmaf(fmaxf(dis * (a1.w + 2.f * s1.w) + sB[7], 0.f), sWo[7], acc);
    acc = fmaf(fmaxf(dis * (a2.x + 2.f * s2.x) + sB[8], 0.f), sWo[8], acc);
    acc = fmaf(fmaxf(dis * (a2.y + 2.f * s2.y) + sB[9], 0.f), sWo[9], acc);
    out[n] = acc;
}

extern "C" void kernel_launch(void* const* d_in, const int* in_sizes, int n_in,
                              void* d_out, int out_size) {
    const float* x    = (const float*)d_in[0];
    const int*   ei   = (const int*)  d_in[1];
    const float* Win  = (const float*)d_in[2];
    const float* bin  = (const float*)d_in[3];
    const float* W1   = (const float*)d_in[4];
    const float* b1   = (const float*)d_in[5];
    const float* W2   = (const float*)d_in[6];
    const float* b2   = (const float*)d_in[7];
    const float* Wout = (const float*)d_in[8];
    const float* bout = (const float*)d_in[9];
    float* out = (float*)d_out;

    void *cnt_p = nullptr, *hwA_p = nullptr, *hwB_p = nullptr;
    cudaGetSymbolAddress(&cnt_p, g_cnt);
    cudaGetSymbolAddress(&hwA_p, g_hwA);
    cudaGetSymbolAddress(&hwB_p, g_hwB);

    static cudaStream_t s1 = nullptr;
    static cudaEvent_t evFork = nullptr, evJoin = nullptr;
    if (s1 == nullptr) {
        cudaStreamCreateWithFlags(&s1, cudaStreamNonBlocking);
        cudaEventCreateWithFlags(&evFork, cudaEventDisableTiming);
        cudaEventCreateWithFlags(&evJoin, cudaEventDisableTiming);
    }

    const int TB = 256;
    int eb = (N_EDGES + TB - 1) / TB;
    int ib = (N_NODES / 2 + TB - 1) / TB;
    int sc = (N_NODES * 4 + TB - 1) / TB;
    int nb = (N_NODES + TB - 1) / TB;
    int gb = N_NODES / 8;

    // Fork: side stream runs the graph-independent input GEMV chain
    cudaEventRecord(evFork, 0);
    cudaStreamWaitEvent(s1, evFork, 0);
    k_input<<<ib, TB, 0, s1>>>(x, Win, bin, W1);
    cudaEventRecord(evJoin, s1);

    // Main stream: build buckets (concurrent with k_input)
    cudaMemsetAsync(cnt_p, 0, (size_t)N_NODES * sizeof(int));
    k_scatter<<<eb, TB>>>(ei);

    // Join, then scale + gather/finalize pairs
    cudaStreamWaitEvent(0, evJoin, 0);
    k_scale<<<sc, TB>>>();
    k_gath<<<gb, TB>>>((const float4*)hwA_p);
    k_fin1<<<nb, TB>>>(b1, W2);
    k_gath<<<gb, TB>>>((const float4*)hwB_p);
    k_fin2<<<nb, TB>>>(b2, Wout, bout, out);
}